// round 8
// baseline (speedup 1.0000x reference)
#include <cuda_runtime.h>
#include <math.h>
#include <stdint.h>

// ---------------- problem constants ----------------
#define BB   2
#define DIM  256
#define NH   8
#define HD   32
#define NL   4
#define NP   4
#define HID  1024
#define NQ   5440
#define MROWS (BB*NQ)   // 10880 = 85*128

__device__ __constant__ int LVL_SIZE[4]  = {64, 32, 16, 8};
__device__ __constant__ int LVL_START[4] = {0, 4096, 5120, 5376};

// ---------------- scratch ----------------
__device__ float g_query[(size_t)MROWS * DIM];
__device__ float g_value[(size_t)MROWS * DIM];
__device__ float g_vn   [(size_t)MROWS * DIM];
__device__ float g_val  [(size_t)MROWS * DIM];
__device__ float g_offaw[(size_t)MROWS * 384];
__device__ float g_samp [(size_t)MROWS * DIM];
__device__ float g_x    [(size_t)MROWS * DIM];
__device__ float g_h1   [(size_t)MROWS * HID];
__device__ float g_h2   [(size_t)MROWS * HID];
// transposed weights [N, K]
__device__ float g_WT_val  [DIM * DIM];
__device__ float g_WT_offaw[384 * DIM];   // rows 0..255 = W_off^T, 256..383 = W_attn^T
__device__ float g_b_offaw [384];
__device__ float g_WT_out  [DIM * DIM];
__device__ float g_WT_fc1  [HID * DIM];
__device__ float g_WT_fc2  [DIM * HID];

// ---------------- cp.async helpers ----------------
__device__ __forceinline__ void cp_async16(uint32_t smem, const void* gmem) {
    asm volatile("cp.async.cg.shared.global [%0], [%1], 16;" :: "r"(smem), "l"(gmem));
}
#define CP_COMMIT() asm volatile("cp.async.commit_group;")
#define CP_WAIT0()  asm volatile("cp.async.wait_group 0;")

// ---------------- mma.sync m16n8k8 tf32 ----------------
__device__ __forceinline__ void mma_tf32(float* d, const uint32_t* a, const uint32_t* b) {
    asm volatile(
        "mma.sync.aligned.m16n8k8.row.col.f32.tf32.tf32.f32 "
        "{%0,%1,%2,%3}, {%4,%5,%6,%7}, {%8,%9}, {%0,%1,%2,%3};\n"
        : "+f"(d[0]), "+f"(d[1]), "+f"(d[2]), "+f"(d[3])
        : "r"(a[0]), "r"(a[1]), "r"(a[2]), "r"(a[3]), "r"(b[0]), "r"(b[1]));
}

// ---------------- TF32 tensor-core GEMM ----------------
// C[M,N] = A[M,K] @ B[K,N] + bias (+resid); B supplied transposed WT[N,K].
// Block tile 128x128, BK=32, 128 threads (4 warps, 2x2 grid, warp tile 64x64).
// grid = (N/128, M/128). Requires M%128==0, N%128==0, K%32==0.
#define LDK 36

__global__ void __launch_bounds__(128)
mma_gemm_kernel(const float* __restrict__ A, const float* __restrict__ WT,
                const float* __restrict__ bias, const float* __restrict__ resid,
                float* __restrict__ C, int N, int K) {
    extern __shared__ float smem[];
    float* Bsmem = smem + 2 * 128 * LDK;

    const int t = threadIdx.x;
    const int lane = t & 31;
    const int wid  = t >> 5;        // 0..3
    const int wm = (wid & 1) * 64;  // warp row offset
    const int wn = (wid >> 1) * 64; // warp col offset
    const int g   = lane >> 2;      // 0..7
    const int tig = lane & 3;       // 0..3
    const int row0 = blockIdx.y * 128;
    const int col0 = blockIdx.x * 128;

    const uint32_t as_u = (uint32_t)__cvta_generic_to_shared(smem);
    const uint32_t bs_u = (uint32_t)__cvta_generic_to_shared(Bsmem);

    // load mapping: 128 threads fill 128 rows x 32 floats (8 float4s each for A and B)
    const int lm = t >> 3;          // 0..15
    const int lq = (t & 7) << 2;    // 0,4,...,28

    float acc[4][8][4];
    #pragma unroll
    for (int i = 0; i < 4; i++)
        #pragma unroll
        for (int j = 0; j < 8; j++)
            #pragma unroll
            for (int r = 0; r < 4; r++) acc[i][j][r] = 0.f;

    const int NC = K >> 5;

    {
        #pragma unroll
        for (int j = 0; j < 8; j++) {
            int m = lm + j * 16;
            cp_async16(as_u + (uint32_t)((m * LDK + lq) * 4),
                       A + (size_t)(row0 + m) * K + lq);
            cp_async16(bs_u + (uint32_t)((m * LDK + lq) * 4),
                       WT + (size_t)(col0 + m) * K + lq);
        }
        CP_COMMIT();
    }

    for (int c = 0; c < NC; c++) {
        const int s = c & 1;
        CP_WAIT0();
        __syncthreads();
        if (c + 1 < NC) {
            const int so = (s ^ 1) * 128 * LDK;
            const int k0 = (c + 1) << 5;
            #pragma unroll
            for (int j = 0; j < 8; j++) {
                int m = lm + j * 16;
                cp_async16(as_u + (uint32_t)((so + m * LDK + lq) * 4),
                           A + (size_t)(row0 + m) * K + k0 + lq);
                cp_async16(bs_u + (uint32_t)((so + m * LDK + lq) * 4),
                           WT + (size_t)(col0 + m) * K + k0 + lq);
            }
            CP_COMMIT();
        }
        const float* Asb = smem  + s * 128 * LDK;
        const float* Bsb = Bsmem + s * 128 * LDK;
        #pragma unroll
        for (int k8 = 0; k8 < 32; k8 += 8) {
            uint32_t bfr[8][2];
            #pragma unroll
            for (int nt = 0; nt < 8; nt++) {
                const float* p = Bsb + (wn + nt * 8 + g) * LDK + k8 + tig;
                bfr[nt][0] = __float_as_uint(p[0]);
                bfr[nt][1] = __float_as_uint(p[4]);
            }
            #pragma unroll
            for (int mt = 0; mt < 4; mt++) {
                const float* p = Asb + (wm + mt * 16 + g) * LDK + k8 + tig;
                uint32_t afr[4];
                afr[0] = __float_as_uint(p[0]);
                afr[1] = __float_as_uint(p[8 * LDK]);
                afr[2] = __float_as_uint(p[4]);
                afr[3] = __float_as_uint(p[8 * LDK + 4]);
                #pragma unroll
                for (int nt = 0; nt < 8; nt++) mma_tf32(acc[mt][nt], afr, bfr[nt]);
            }
        }
        __syncthreads();
    }

    #pragma unroll
    for (int mt = 0; mt < 4; mt++) {
        int r0 = row0 + wm + mt * 16 + g;
        #pragma unroll
        for (int nt = 0; nt < 8; nt++) {
            int cc = col0 + wn + nt * 8 + tig * 2;
            float2 bv = *(const float2*)(bias + cc);
            float2 v0, v1;
            v0.x = acc[mt][nt][0] + bv.x;
            v0.y = acc[mt][nt][1] + bv.y;
            v1.x = acc[mt][nt][2] + bv.x;
            v1.y = acc[mt][nt][3] + bv.y;
            if (resid) {
                float2 ra = *(const float2*)(resid + (size_t)r0 * N + cc);
                float2 rb = *(const float2*)(resid + (size_t)(r0 + 8) * N + cc);
                v0.x += ra.x; v0.y += ra.y;
                v1.x += rb.x; v1.y += rb.y;
            }
            *(float2*)(C + (size_t)r0 * N + cc)       = v0;
            *(float2*)(C + (size_t)(r0 + 8) * N + cc) = v1;
        }
    }
}

#define GEMM_SMEM_BYTES (4u * 128u * LDK * 4u)   // 73728 B

// ---------------- combined transpose of all 6 weights + bias concat ----------------
__global__ void __launch_bounds__(256)
transpose_all_kernel(const float* __restrict__ s_val, const float* __restrict__ s_off,
                     const float* __restrict__ s_attn, const float* __restrict__ s_out,
                     const float* __restrict__ s_fc1, const float* __restrict__ s_fc2,
                     const float* __restrict__ b_off, const float* __restrict__ b_attn,
                     float* __restrict__ d_val, float* __restrict__ d_offaw,
                     float* __restrict__ d_out, float* __restrict__ d_fc1,
                     float* __restrict__ d_fc2, float* __restrict__ d_b_offaw) {
    int u = blockIdx.x;
    int t = threadIdx.x;
    if (u == 736) {
        if (t < 128) {
            d_b_offaw[t]       = b_off[t];
            d_b_offaw[t + 128] = b_off[t + 128];
        } else {
            int j = t - 128;
            d_b_offaw[256 + j] = b_attn[j];
        }
        return;
    }
    const float* src; float* dst; int K, N;
    if      (u < 64)  {            src = s_val;  dst = d_val;            K = 256;  N = 256; }
    else if (u < 128) { u -= 64;   src = s_off;  dst = d_offaw;          K = 256;  N = 256; }
    else if (u < 160) { u -= 128;  src = s_attn; dst = d_offaw + 256*256; K = 256; N = 128; }
    else if (u < 224) { u -= 160;  src = s_out;  dst = d_out;            K = 256;  N = 256; }
    else if (u < 480) { u -= 224;  src = s_fc1;  dst = d_fc1;            K = 256;  N = 1024; }
    else              { u -= 480;  src = s_fc2;  dst = d_fc2;            K = 1024; N = 256; }
    int nt = N >> 5;
    int by = (u / nt) * 32, bx = (u % nt) * 32;
    __shared__ float tile[32][33];
    int tx = t & 31, ty = t >> 5;   // 32 x 8
    #pragma unroll
    for (int i = 0; i < 32; i += 8)
        tile[ty + i][tx] = src[(size_t)(by + ty + i) * N + bx + tx];
    __syncthreads();
    #pragma unroll
    for (int i = 0; i < 32; i += 8)
        dst[(size_t)(bx + ty + i) * K + by + tx] = tile[tx][ty + i];
}

// ---------------- combined flatten (coalesced tile transpose) ----------------
__global__ void __launch_bounds__(256)
flatten_all_kernel(const float* __restrict__ q0, const float* __restrict__ v0,
                   const float* __restrict__ q1, const float* __restrict__ v1,
                   const float* __restrict__ q2, const float* __restrict__ v2,
                   const float* __restrict__ q3, const float* __restrict__ v3,
                   float* __restrict__ gq, float* __restrict__ gv) {
    __shared__ float tq[32][33], tv[32][33];
    int blk = blockIdx.x;
    int b = blk / 1360;
    int u = blk % 1360;
    const float *qs, *vs; int n, start;
    if      (u < 1024) {            qs = q0; vs = v0; n = 4096; start = 0; }
    else if (u < 1280) { u -= 1024; qs = q1; vs = v1; n = 1024; start = 4096; }
    else if (u < 1344) { u -= 1280; qs = q2; vs = v2; n = 256;  start = 5120; }
    else               { u -= 1344; qs = q3; vs = v3; n = 64;   start = 5376; }
    int pt = n >> 5;
    int ct = u / pt;
    int pi = u % pt;
    int t = threadIdx.x;
    int tx = t & 31, ty = t >> 5;
    const float* qb = qs + (size_t)(b * DIM + ct * 32) * n + pi * 32;
    const float* vb = vs + (size_t)(b * DIM + ct * 32) * n + pi * 32;
    #pragma unroll
    for (int i = 0; i < 32; i += 8) {
        tq[ty + i][tx] = qb[(size_t)(ty + i) * n + tx];
        tv[ty + i][tx] = vb[(size_t)(ty + i) * n + tx];
    }
    __syncthreads();
    size_t obase = ((size_t)b * NQ + start + pi * 32) * DIM + ct * 32;
    #pragma unroll
    for (int i = 0; i < 32; i += 8) {
        gq[obase + (size_t)(ty + i) * DIM + tx] = tq[tx][ty + i];
        gv[obase + (size_t)(ty + i) * DIM + tx] = tv[tx][ty + i];
    }
}

// ---------------- layernorm ----------------
__global__ void layernorm_kernel(const float* __restrict__ x, const float* __restrict__ g,
                                 const float* __restrict__ bia, float* __restrict__ out) {
    int row = blockIdx.x;
    int t = threadIdx.x;
    float v = x[(size_t)row * DIM + t];
    __shared__ float sm[40];
    float s = v;
    #pragma unroll
    for (int o = 16; o > 0; o >>= 1) s += __shfl_xor_sync(0xffffffffu, s, o);
    if ((t & 31) == 0) sm[t >> 5] = s;
    __syncthreads();
    if (t < 8) {
        float z = sm[t];
        #pragma unroll
        for (int o = 4; o > 0; o >>= 1) z += __shfl_xor_sync(0xffu, z, o);
        if (t == 0) sm[32] = z;
    }
    __syncthreads();
    float mean = sm[32] * (1.0f / DIM);
    float d = v - mean;
    float s2 = d * d;
    #pragma unroll
    for (int o = 16; o > 0; o >>= 1) s2 += __shfl_xor_sync(0xffffffffu, s2, o);
    if ((t & 31) == 0) sm[8 + (t >> 5)] = s2;
    __syncthreads();
    if (t < 8) {
        float z = sm[8 + t];
        #pragma unroll
        for (int o = 4; o > 0; o >>= 1) z += __shfl_xor_sync(0xffu, z, o);
        if (t == 0) sm[33] = z;
    }
    __syncthreads();
    float var = sm[33] * (1.0f / DIM);
    out[(size_t)row * DIM + t] = d * rsqrtf(var + 1e-5f) * g[t] + bia[t];
}

// ---------------- deformable sampling with fused softmax --------------------
__global__ void __launch_bounds__(256)
deform_kernel(const float* __restrict__ val, const float* __restrict__ offaw,
              float* __restrict__ samp) {
    int gw = (blockIdx.x * blockDim.x + threadIdx.x) >> 5;
    int lane = threadIdx.x & 31;
    if (gw >= MROWS * NH) return;
    int hh = gw % NH;
    int q  = (gw / NH) % NQ;
    int b  = gw / (NH * NQ);

    int lqv, local;
    if (q < 4096)      { lqv = 0; local = q; }
    else if (q < 5120) { lqv = 1; local = q - 4096; }
    else if (q < 5376) { lqv = 2; local = q - 5120; }
    else               { lqv = 3; local = q - 5376; }
    int szq = LVL_SIZE[lqv];
    float refx = ((local % szq) + 0.5f) / szq;
    float refy = ((local / szq) + 0.5f) / szq;

    const float* rowp = offaw + (size_t)(b * NQ + q) * 384;
    const float* offp = rowp + hh * 32;
    const float* awp  = rowp + 256 + hh * 16;

    float awv[16];
    float mx = -1e30f;
    #pragma unroll
    for (int j = 0; j < 16; j++) { awv[j] = awp[j]; mx = fmaxf(mx, awv[j]); }
    float ssum = 0.f;
    #pragma unroll
    for (int j = 0; j < 16; j++) { awv[j] = __expf(awv[j] - mx); ssum += awv[j]; }
    float sinv = 1.0f / ssum;

    float acc = 0.f;
    #pragma unroll
    for (int l = 0; l < NL; l++) {
        int w = LVL_SIZE[l];
        int startl = LVL_START[l];
        const float* vbase = val + ((size_t)b * NQ + startl) * DIM + hh * HD + lane;
        float inv = 1.0f / (float)w;
        #pragma unroll
        for (int p = 0; p < NP; p++) {
            float ox = offp[(l * NP + p) * 2 + 0];
            float oy = offp[(l * NP + p) * 2 + 1];
            float a  = awv[l * NP + p] * sinv;
            float sx = (refx + ox * inv) * w - 0.5f;
            float sy = (refy + oy * inv) * w - 0.5f;
            int x0 = (int)floorf(sx);
            int y0 = (int)floorf(sy);
            float lx = sx - (float)x0;
            float ly = sy - (float)y0;
            float w00 = (1.f - lx) * (1.f - ly);
            float w10 = lx * (1.f - ly);
            float w01 = (1.f - lx) * ly;
            float w11 = lx * ly;
            float g = 0.f;
            if (x0 >= 0 && x0 < w && y0 >= 0 && y0 < w)
                g += w00 * vbase[(size_t)(y0 * w + x0) * DIM];
            if (x0 + 1 >= 0 && x0 + 1 < w && y0 >= 0 && y0 < w)
                g += w10 * vbase[(size_t)(y0 * w + x0 + 1) * DIM];
            if (x0 >= 0 && x0 < w && y0 + 1 >= 0 && y0 + 1 < w)
                g += w01 * vbase[(size_t)((y0 + 1) * w + x0) * DIM];
            if (x0 + 1 >= 0 && x0 + 1 < w && y0 + 1 >= 0 && y0 + 1 < w)
                g += w11 * vbase[(size_t)((y0 + 1) * w + x0 + 1) * DIM];
            acc = fmaf(a, g, acc);
        }
    }
    samp[(size_t)(b * NQ + q) * DIM + hh * HD + lane] = acc;
}

// ---------------- depthwise 3x3 + bias + GELU, smem-tiled ----------------
__global__ void __launch_bounds__(256)
dwconv_gelu_tiled(const float* __restrict__ h1, const float* __restrict__ Wdw,
                  const float* __restrict__ bdw, float* __restrict__ h2) {
    extern __shared__ float ts[];   // [100][128]
    int tile = blockIdx.x;
    int c0 = blockIdx.y * 128;
    int b = blockIdx.z;
    int l, tx, ty;
    if      (tile < 64) { l = 0; ty = tile >> 3; tx = tile & 7; }
    else if (tile < 80) { int u = tile - 64; l = 1; ty = u >> 2; tx = u & 3; }
    else if (tile < 84) { int u = tile - 80; l = 2; ty = u >> 1; tx = u & 1; }
    else                { l = 3; ty = 0; tx = 0; }
    int w = LVL_SIZE[l];
    int start = LVL_START[l];
    int t = threadIdx.x;
    int c = t & 127;
    int half = t >> 7;

    const float* hbase = h1 + ((size_t)b * NQ + start) * HID + c0 + c;
    for (int p = half; p < 100; p += 2) {
        int py = p / 10 - 1 + ty * 8;
        int px = p % 10 - 1 + tx * 8;
        float v = 0.f;
        if (py >= 0 && py < w && px >= 0 && px < w)
            v = hbase[(size_t)(py * w + px) * HID];
        ts[p * 128 + c] = v;
    }
    float w9[9];
    #pragma unroll
    for (int j = 0; j < 9; j++) w9[j] = Wdw[j * HID + c0 + c];
    float bs = bdw[c0 + c];
    __syncthreads();

    float* obase = h2 + ((size_t)b * NQ + start + (ty * 8) * w + tx * 8) * HID + c0 + c;
    for (int p = half; p < 64; p += 2) {
        int py = p >> 3, px = p & 7;
        float acc = bs;
        #pragma unroll
        for (int ky = 0; ky < 3; ky++)
            #pragma unroll
            for (int kx = 0; kx < 3; kx++)
                acc = fmaf(ts[((py + ky) * 10 + px + kx) * 128 + c], w9[ky * 3 + kx], acc);
        float gelu = acc * 0.5f * (1.0f + erff(acc * 0.70710678118654752440f));
        obase[(size_t)(py * w + px) * HID] = gelu;
    }
}
#define DW_SMEM_BYTES (100u * 128u * 4u)   // 51200

// ---------------- launch ----------------
extern "C" void kernel_launch(void* const* d_in, const int* in_sizes, int n_in,
                              void* d_out, int out_size) {
    const float* q0 = (const float*)d_in[0];
    const float* v0 = (const float*)d_in[1];
    const float* q1 = (const float*)d_in[2];
    const float* v1 = (const float*)d_in[3];
    const float* q2 = (const float*)d_in[4];
    const float* v2 = (const float*)d_in[5];
    const float* q3 = (const float*)d_in[6];
    const float* v3 = (const float*)d_in[7];
    const float* vn_g  = (const float*)d_in[8];
    const float* vn_b  = (const float*)d_in[9];
    const float* W_off = (const float*)d_in[10];
    const float* b_off = (const float*)d_in[11];
    const float* W_attn= (const float*)d_in[12];
    const float* b_attn= (const float*)d_in[13];
    const float* W_val = (const float*)d_in[14];
    const float* b_val = (const float*)d_in[15];
    const float* W_out = (const float*)d_in[16];
    const float* b_out = (const float*)d_in[17];
    const float* W_fc1 = (const float*)d_in[18];
    const float* b_fc1 = (const float*)d_in[19];
    const float* W_dw  = (const float*)d_in[20];
    const float* b_dw  = (const float*)d_in[21];
    const float* W_fc2 = (const float*)d_in[22];
    const float* b_fc2 = (const float*)d_in[23];
    float* out = (float*)d_out;

    float *gq, *gv, *gvn, *gval, *goffaw, *gsamp, *gx, *gh1, *gh2;
    float *wtval, *wtoffaw, *boffaw, *wtout, *wtfc1, *wtfc2;
    cudaGetSymbolAddress((void**)&gq,     g_query);
    cudaGetSymbolAddress((void**)&gv,     g_value);
    cudaGetSymbolAddress((void**)&gvn,    g_vn);
    cudaGetSymbolAddress((void**)&gval,   g_val);
    cudaGetSymbolAddress((void**)&goffaw, g_offaw);
    cudaGetSymbolAddress((void**)&gsamp,  g_samp);
    cudaGetSymbolAddress((void**)&gx,     g_x);
    cudaGetSymbolAddress((void**)&gh1,    g_h1);
    cudaGetSymbolAddress((void**)&gh2,    g_h2);
    cudaGetSymbolAddress((void**)&wtval,  g_WT_val);
    cudaGetSymbolAddress((void**)&wtoffaw,g_WT_offaw);
    cudaGetSymbolAddress((void**)&boffaw, g_b_offaw);
    cudaGetSymbolAddress((void**)&wtout,  g_WT_out);
    cudaGetSymbolAddress((void**)&wtfc1,  g_WT_fc1);
    cudaGetSymbolAddress((void**)&wtfc2,  g_WT_fc2);

    cudaFuncSetAttribute(mma_gemm_kernel,
                         cudaFuncAttributeMaxDynamicSharedMemorySize, GEMM_SMEM_BYTES);
    cudaFuncSetAttribute(dwconv_gelu_tiled,
                         cudaFuncAttributeMaxDynamicSharedMemorySize, DW_SMEM_BYTES);

    transpose_all_kernel<<<737, 256>>>(W_val, W_off, W_attn, W_out, W_fc1, W_fc2,
                                       b_off, b_attn,
                                       wtval, wtoffaw, wtout, wtfc1, wtfc2, boffaw);

    flatten_all_kernel<<<2720, 256>>>(q0, v0, q1, v1, q2, v2, q3, v3, gq, gv);

    layernorm_kernel<<<MROWS, 256>>>(gv, vn_g, vn_b, gvn);

    const int MT = MROWS / 128;  // 85
    // val = LN(value) @ W_val + b_val
    mma_gemm_kernel<<<dim3(2, MT), 128, GEMM_SMEM_BYTES>>>(gvn, wtval, b_val, nullptr, gval, DIM, DIM);
    // [off | aw_raw] = query @ [W_off | W_attn] + [b_off | b_attn]
    mma_gemm_kernel<<<dim3(3, MT), 128, GEMM_SMEM_BYTES>>>(gq, wtoffaw, boffaw, nullptr, goffaw, 384, DIM);

    // sampling (softmax fused)
    deform_kernel<<<(MROWS * NH * 32 + 255) / 256, 256>>>(gval, goffaw, gsamp);

    // x = query + samp @ W_out + b_out
    mma_gemm_kernel<<<dim3(2, MT), 128, GEMM_SMEM_BYTES>>>(gsamp, wtout, b_out, gq, gx, DIM, DIM);
    // h1 = x @ W_fc1 + b_fc1
    mma_gemm_kernel<<<dim3(8, MT), 128, GEMM_SMEM_BYTES>>>(gx, wtfc1, b_fc1, nullptr, gh1, HID, DIM);

    // h2 = gelu(dwconv(h1) + b_dw), smem-tiled
    dwconv_gelu_tiled<<<dim3(85, 8, BB), 256, DW_SMEM_BYTES>>>(gh1, W_dw, b_dw, gh2);

    // out = x + h2 @ W_fc2 + b_fc2
    mma_gemm_kernel<<<dim3(2, MT), 128, GEMM_SMEM_BYTES>>>(gh2, wtfc2, b_fc2, gx, out, DIM, HID);
}

// round 9
// speedup vs baseline: 1.0114x; 1.0114x over previous
#include <cuda_runtime.h>
#include <math.h>
#include <stdint.h>

// ---------------- problem constants ----------------
#define BB   2
#define DIM  256
#define NH   8
#define HD   32
#define NL   4
#define NP   4
#define HID  1024
#define NQ   5440
#define MROWS (BB*NQ)   // 10880 = 85*128

__device__ __constant__ int LVL_SIZE[4]  = {64, 32, 16, 8};
__device__ __constant__ int LVL_START[4] = {0, 4096, 5120, 5376};

// ---------------- scratch ----------------
__device__ float g_query[(size_t)MROWS * DIM];
__device__ float g_value[(size_t)MROWS * DIM];
__device__ float g_vn   [(size_t)MROWS * DIM];
__device__ float g_val  [(size_t)MROWS * DIM];
__device__ float g_offaw[(size_t)MROWS * 384];
__device__ float g_samp [(size_t)MROWS * DIM];
__device__ float g_x    [(size_t)MROWS * DIM];
__device__ float g_h1   [(size_t)MROWS * HID];
__device__ float g_h2   [(size_t)MROWS * HID];
// transposed weights [N, K]
__device__ float g_WT_val  [DIM * DIM];
__device__ float g_WT_offaw[384 * DIM];
__device__ float g_b_offaw [384];
__device__ float g_WT_out  [DIM * DIM];
__device__ float g_WT_fc1  [HID * DIM];
__device__ float g_WT_fc2  [DIM * HID];

// ---------------- cp.async helpers ----------------
__device__ __forceinline__ void cp_async16(uint32_t smem, const void* gmem) {
    asm volatile("cp.async.cg.shared.global [%0], [%1], 16;" :: "r"(smem), "l"(gmem));
}
#define CP_COMMIT() asm volatile("cp.async.commit_group;")
#define CP_WAIT0()  asm volatile("cp.async.wait_group 0;")
#define CP_WAIT1()  asm volatile("cp.async.wait_group 1;")

// ---------------- mma.sync m16n8k8 tf32 ----------------
__device__ __forceinline__ void mma_tf32(float* d, const uint32_t* a, const uint32_t* b) {
    asm volatile(
        "mma.sync.aligned.m16n8k8.row.col.f32.tf32.tf32.f32 "
        "{%0,%1,%2,%3}, {%4,%5,%6,%7}, {%8,%9}, {%0,%1,%2,%3};\n"
        : "+f"(d[0]), "+f"(d[1]), "+f"(d[2]), "+f"(d[3])
        : "r"(a[0]), "r"(a[1]), "r"(a[2]), "r"(a[3]), "r"(b[0]), "r"(b[1]));
}

// ---------------- TF32 tensor-core GEMM, 3-stage cp.async pipeline ----------------
// C[M,N] = A[M,K] @ B[K,N] + bias (+resid); B supplied transposed WT[N,K].
// Block tile 128x128, BK=32, 256 threads (8 warps, warp tile 64x32), 3 smem stages.
// grid = (N/128, M/128). Requires M%128==0, N%128==0, K%32==0, K/32 >= 2.
#define LDK 36
#define STG 3
#define STAGE_F (128 * LDK)          // floats per (A or B) stage

__global__ void __launch_bounds__(256, 2)
mma_gemm_kernel(const float* __restrict__ A, const float* __restrict__ WT,
                const float* __restrict__ bias, const float* __restrict__ resid,
                float* __restrict__ C, int N, int K) {
    extern __shared__ float smem[];
    float* Bsmem = smem + STG * STAGE_F;

    const int t = threadIdx.x;
    const int lane = t & 31;
    const int wid  = t >> 5;
    const int wm = (wid & 1) * 64;
    const int wn = (wid >> 1) * 32;
    const int g   = lane >> 2;
    const int tig = lane & 3;
    const int row0 = blockIdx.y * 128;
    const int col0 = blockIdx.x * 128;

    const uint32_t as_u = (uint32_t)__cvta_generic_to_shared(smem);
    const uint32_t bs_u = (uint32_t)__cvta_generic_to_shared(Bsmem);

    // load mapping: 256 threads fill 128 rows x 32 floats (4 float4s each for A and B)
    const int lm = t >> 3;          // 0..31
    const int lq = (t & 7) << 2;    // 0,4,...,28

    float acc[4][4][4];
    #pragma unroll
    for (int i = 0; i < 4; i++)
        #pragma unroll
        for (int j = 0; j < 4; j++)
            #pragma unroll
            for (int r = 0; r < 4; r++) acc[i][j][r] = 0.f;

    const int NC = K >> 5;

    // prologue: prefetch chunks 0 and 1 into stages 0 and 1
    #pragma unroll
    for (int pc = 0; pc < 2; pc++) {
        const int so = pc * STAGE_F;
        const int k0 = pc << 5;
        #pragma unroll
        for (int j = 0; j < 4; j++) {
            int m = lm + j * 32;
            cp_async16(as_u + (uint32_t)((so + m * LDK + lq) * 4),
                       A + (size_t)(row0 + m) * K + k0 + lq);
            cp_async16(bs_u + (uint32_t)((so + m * LDK + lq) * 4),
                       WT + (size_t)(col0 + m) * K + k0 + lq);
        }
        CP_COMMIT();
    }

    int stage = 0;
    int pstage = 2;   // stage that chunk c+2 goes into
    for (int c = 0; c < NC; c++) {
        if (c == NC - 1) { CP_WAIT0(); } else { CP_WAIT1(); }
        __syncthreads();
        if (c + 2 < NC) {
            const int so = pstage * STAGE_F;
            const int k0 = (c + 2) << 5;
            #pragma unroll
            for (int j = 0; j < 4; j++) {
                int m = lm + j * 32;
                cp_async16(as_u + (uint32_t)((so + m * LDK + lq) * 4),
                           A + (size_t)(row0 + m) * K + k0 + lq);
                cp_async16(bs_u + (uint32_t)((so + m * LDK + lq) * 4),
                           WT + (size_t)(col0 + m) * K + k0 + lq);
            }
            CP_COMMIT();
        }
        const float* Asb = smem  + stage * STAGE_F;
        const float* Bsb = Bsmem + stage * STAGE_F;
        #pragma unroll
        for (int k8 = 0; k8 < 32; k8 += 8) {
            uint32_t bfr[4][2];
            #pragma unroll
            for (int nt = 0; nt < 4; nt++) {
                const float* p = Bsb + (wn + nt * 8 + g) * LDK + k8 + tig;
                bfr[nt][0] = __float_as_uint(p[0]);
                bfr[nt][1] = __float_as_uint(p[4]);
            }
            #pragma unroll
            for (int mt = 0; mt < 4; mt++) {
                const float* p = Asb + (wm + mt * 16 + g) * LDK + k8 + tig;
                uint32_t afr[4];
                afr[0] = __float_as_uint(p[0]);
                afr[1] = __float_as_uint(p[8 * LDK]);
                afr[2] = __float_as_uint(p[4]);
                afr[3] = __float_as_uint(p[8 * LDK + 4]);
                #pragma unroll
                for (int nt = 0; nt < 4; nt++) mma_tf32(acc[mt][nt], afr, bfr[nt]);
            }
        }
        stage = (stage == STG - 1) ? 0 : stage + 1;
        pstage = (pstage == STG - 1) ? 0 : pstage + 1;
    }
    __syncthreads();

    #pragma unroll
    for (int mt = 0; mt < 4; mt++) {
        int r0 = row0 + wm + mt * 16 + g;
        #pragma unroll
        for (int nt = 0; nt < 4; nt++) {
            int cc = col0 + wn + nt * 8 + tig * 2;
            float2 bv = *(const float2*)(bias + cc);
            float2 v0, v1;
            v0.x = acc[mt][nt][0] + bv.x;
            v0.y = acc[mt][nt][1] + bv.y;
            v1.x = acc[mt][nt][2] + bv.x;
            v1.y = acc[mt][nt][3] + bv.y;
            if (resid) {
                float2 ra = *(const float2*)(resid + (size_t)r0 * N + cc);
                float2 rb = *(const float2*)(resid + (size_t)(r0 + 8) * N + cc);
                v0.x += ra.x; v0.y += ra.y;
                v1.x += rb.x; v1.y += rb.y;
            }
            *(float2*)(C + (size_t)r0 * N + cc)       = v0;
            *(float2*)(C + (size_t)(r0 + 8) * N + cc) = v1;
        }
    }
}

#define GEMM_SMEM_BYTES (2u * STG * STAGE_F * 4u)   // 110592 B

// ---------------- combined transpose of all 6 weights + bias concat ----------------
__global__ void __launch_bounds__(256)
transpose_all_kernel(const float* __restrict__ s_val, const float* __restrict__ s_off,
                     const float* __restrict__ s_attn, const float* __restrict__ s_out,
                     const float* __restrict__ s_fc1, const float* __restrict__ s_fc2,
                     const float* __restrict__ b_off, const float* __restrict__ b_attn,
                     float* __restrict__ d_val, float* __restrict__ d_offaw,
                     float* __restrict__ d_out, float* __restrict__ d_fc1,
                     float* __restrict__ d_fc2, float* __restrict__ d_b_offaw) {
    int u = blockIdx.x;
    int t = threadIdx.x;
    if (u == 736) {
        if (t < 128) {
            d_b_offaw[t]       = b_off[t];
            d_b_offaw[t + 128] = b_off[t + 128];
        } else {
            int j = t - 128;
            d_b_offaw[256 + j] = b_attn[j];
        }
        return;
    }
    const float* src; float* dst; int K, N;
    if      (u < 64)  {            src = s_val;  dst = d_val;            K = 256;  N = 256; }
    else if (u < 128) { u -= 64;   src = s_off;  dst = d_offaw;          K = 256;  N = 256; }
    else if (u < 160) { u -= 128;  src = s_attn; dst = d_offaw + 256*256; K = 256; N = 128; }
    else if (u < 224) { u -= 160;  src = s_out;  dst = d_out;            K = 256;  N = 256; }
    else if (u < 480) { u -= 224;  src = s_fc1;  dst = d_fc1;            K = 256;  N = 1024; }
    else              { u -= 480;  src = s_fc2;  dst = d_fc2;            K = 1024; N = 256; }
    int nt = N >> 5;
    int by = (u / nt) * 32, bx = (u % nt) * 32;
    __shared__ float tile[32][33];
    int tx = t & 31, ty = t >> 5;   // 32 x 8
    #pragma unroll
    for (int i = 0; i < 32; i += 8)
        tile[ty + i][tx] = src[(size_t)(by + ty + i) * N + bx + tx];
    __syncthreads();
    #pragma unroll
    for (int i = 0; i < 32; i += 8)
        dst[(size_t)(bx + ty + i) * K + by + tx] = tile[tx][ty + i];
}

// ---------------- combined flatten (coalesced tile transpose) ----------------
__global__ void __launch_bounds__(256)
flatten_all_kernel(const float* __restrict__ q0, const float* __restrict__ v0,
                   const float* __restrict__ q1, const float* __restrict__ v1,
                   const float* __restrict__ q2, const float* __restrict__ v2,
                   const float* __restrict__ q3, const float* __restrict__ v3,
                   float* __restrict__ gq, float* __restrict__ gv) {
    __shared__ float tq[32][33], tv[32][33];
    int blk = blockIdx.x;
    int b = blk / 1360;
    int u = blk % 1360;
    const float *qs, *vs; int n, start;
    if      (u < 1024) {            qs = q0; vs = v0; n = 4096; start = 0; }
    else if (u < 1280) { u -= 1024; qs = q1; vs = v1; n = 1024; start = 4096; }
    else if (u < 1344) { u -= 1280; qs = q2; vs = v2; n = 256;  start = 5120; }
    else               { u -= 1344; qs = q3; vs = v3; n = 64;   start = 5376; }
    int pt = n >> 5;
    int ct = u / pt;
    int pi = u % pt;
    int t = threadIdx.x;
    int tx = t & 31, ty = t >> 5;
    const float* qb = qs + (size_t)(b * DIM + ct * 32) * n + pi * 32;
    const float* vb = vs + (size_t)(b * DIM + ct * 32) * n + pi * 32;
    #pragma unroll
    for (int i = 0; i < 32; i += 8) {
        tq[ty + i][tx] = qb[(size_t)(ty + i) * n + tx];
        tv[ty + i][tx] = vb[(size_t)(ty + i) * n + tx];
    }
    __syncthreads();
    size_t obase = ((size_t)b * NQ + start + pi * 32) * DIM + ct * 32;
    #pragma unroll
    for (int i = 0; i < 32; i += 8) {
        gq[obase + (size_t)(ty + i) * DIM + tx] = tq[tx][ty + i];
        gv[obase + (size_t)(ty + i) * DIM + tx] = tv[tx][ty + i];
    }
}

// ---------------- layernorm ----------------
__global__ void layernorm_kernel(const float* __restrict__ x, const float* __restrict__ g,
                                 const float* __restrict__ bia, float* __restrict__ out) {
    int row = blockIdx.x;
    int t = threadIdx.x;
    float v = x[(size_t)row * DIM + t];
    __shared__ float sm[40];
    float s = v;
    #pragma unroll
    for (int o = 16; o > 0; o >>= 1) s += __shfl_xor_sync(0xffffffffu, s, o);
    if ((t & 31) == 0) sm[t >> 5] = s;
    __syncthreads();
    if (t < 8) {
        float z = sm[t];
        #pragma unroll
        for (int o = 4; o > 0; o >>= 1) z += __shfl_xor_sync(0xffu, z, o);
        if (t == 0) sm[32] = z;
    }
    __syncthreads();
    float mean = sm[32] * (1.0f / DIM);
    float d = v - mean;
    float s2 = d * d;
    #pragma unroll
    for (int o = 16; o > 0; o >>= 1) s2 += __shfl_xor_sync(0xffffffffu, s2, o);
    if ((t & 31) == 0) sm[8 + (t >> 5)] = s2;
    __syncthreads();
    if (t < 8) {
        float z = sm[8 + t];
        #pragma unroll
        for (int o = 4; o > 0; o >>= 1) z += __shfl_xor_sync(0xffu, z, o);
        if (t == 0) sm[33] = z;
    }
    __syncthreads();
    float var = sm[33] * (1.0f / DIM);
    out[(size_t)row * DIM + t] = d * rsqrtf(var + 1e-5f) * g[t] + bia[t];
}

// ---------------- deformable sampling with fused softmax --------------------
__global__ void __launch_bounds__(256)
deform_kernel(const float* __restrict__ val, const float* __restrict__ offaw,
              float* __restrict__ samp) {
    int gw = (blockIdx.x * blockDim.x + threadIdx.x) >> 5;
    int lane = threadIdx.x & 31;
    if (gw >= MROWS * NH) return;
    int hh = gw % NH;
    int q  = (gw / NH) % NQ;
    int b  = gw / (NH * NQ);

    int lqv, local;
    if (q < 4096)      { lqv = 0; local = q; }
    else if (q < 5120) { lqv = 1; local = q - 4096; }
    else if (q < 5376) { lqv = 2; local = q - 5120; }
    else               { lqv = 3; local = q - 5376; }
    int szq = LVL_SIZE[lqv];
    float refx = ((local % szq) + 0.5f) / szq;
    float refy = ((local / szq) + 0.5f) / szq;

    const float* rowp = offaw + (size_t)(b * NQ + q) * 384;
    const float* offp = rowp + hh * 32;
    const float* awp  = rowp + 256 + hh * 16;

    float awv[16];
    float mx = -1e30f;
    #pragma unroll
    for (int j = 0; j < 16; j++) { awv[j] = awp[j]; mx = fmaxf(mx, awv[j]); }
    float ssum = 0.f;
    #pragma unroll
    for (int j = 0; j < 16; j++) { awv[j] = __expf(awv[j] - mx); ssum += awv[j]; }
    float sinv = 1.0f / ssum;

    float acc = 0.f;
    #pragma unroll
    for (int l = 0; l < NL; l++) {
        int w = LVL_SIZE[l];
        int startl = LVL_START[l];
        const float* vbase = val + ((size_t)b * NQ + startl) * DIM + hh * HD + lane;
        float inv = 1.0f / (float)w;
        #pragma unroll
        for (int p = 0; p < NP; p++) {
            float ox = offp[(l * NP + p) * 2 + 0];
            float oy = offp[(l * NP + p) * 2 + 1];
            float a  = awv[l * NP + p] * sinv;
            float sx = (refx + ox * inv) * w - 0.5f;
            float sy = (refy + oy * inv) * w - 0.5f;
            int x0 = (int)floorf(sx);
            int y0 = (int)floorf(sy);
            float lx = sx - (float)x0;
            float ly = sy - (float)y0;
            float w00 = (1.f - lx) * (1.f - ly);
            float w10 = lx * (1.f - ly);
            float w01 = (1.f - lx) * ly;
            float w11 = lx * ly;
            float g = 0.f;
            if (x0 >= 0 && x0 < w && y0 >= 0 && y0 < w)
                g += w00 * vbase[(size_t)(y0 * w + x0) * DIM];
            if (x0 + 1 >= 0 && x0 + 1 < w && y0 >= 0 && y0 < w)
                g += w10 * vbase[(size_t)(y0 * w + x0 + 1) * DIM];
            if (x0 >= 0 && x0 < w && y0 + 1 >= 0 && y0 + 1 < w)
                g += w01 * vbase[(size_t)((y0 + 1) * w + x0) * DIM];
            if (x0 + 1 >= 0 && x0 + 1 < w && y0 + 1 >= 0 && y0 + 1 < w)
                g += w11 * vbase[(size_t)((y0 + 1) * w + x0 + 1) * DIM];
            acc = fmaf(a, g, acc);
        }
    }
    samp[(size_t)(b * NQ + q) * DIM + hh * HD + lane] = acc;
}

// ---------------- depthwise 3x3 + bias + GELU, smem-tiled ----------------
__global__ void __launch_bounds__(256)
dwconv_gelu_tiled(const float* __restrict__ h1, const float* __restrict__ Wdw,
                  const float* __restrict__ bdw, float* __restrict__ h2) {
    extern __shared__ float ts[];   // [100][128]
    int tile = blockIdx.x;
    int c0 = blockIdx.y * 128;
    int b = blockIdx.z;
    int l, tx, ty;
    if      (tile < 64) { l = 0; ty = tile >> 3; tx = tile & 7; }
    else if (tile < 80) { int u = tile - 64; l = 1; ty = u >> 2; tx = u & 3; }
    else if (tile < 84) { int u = tile - 80; l = 2; ty = u >> 1; tx = u & 1; }
    else                { l = 3; ty = 0; tx = 0; }
    int w = LVL_SIZE[l];
    int start = LVL_START[l];
    int t = threadIdx.x;
    int c = t & 127;
    int half = t >> 7;

    const float* hbase = h1 + ((size_t)b * NQ + start) * HID + c0 + c;
    for (int p = half; p < 100; p += 2) {
        int py = p / 10 - 1 + ty * 8;
        int px = p % 10 - 1 + tx * 8;
        float v = 0.f;
        if (py >= 0 && py < w && px >= 0 && px < w)
            v = hbase[(size_t)(py * w + px) * HID];
        ts[p * 128 + c] = v;
    }
    float w9[9];
    #pragma unroll
    for (int j = 0; j < 9; j++) w9[j] = Wdw[j * HID + c0 + c];
    float bs = bdw[c0 + c];
    __syncthreads();

    float* obase = h2 + ((size_t)b * NQ + start + (ty * 8) * w + tx * 8) * HID + c0 + c;
    for (int p = half; p < 64; p += 2) {
        int py = p >> 3, px = p & 7;
        float acc = bs;
        #pragma unroll
        for (int ky = 0; ky < 3; ky++)
            #pragma unroll
            for (int kx = 0; kx < 3; kx++)
                acc = fmaf(ts[((py + ky) * 10 + px + kx) * 128 + c], w9[ky * 3 + kx], acc);
        float gelu = acc * 0.5f * (1.0f + erff(acc * 0.70710678118654752440f));
        obase[(size_t)(py * w + px) * HID] = gelu;
    }
}
#define DW_SMEM_BYTES (100u * 128u * 4u)   // 51200

// ---------------- launch ----------------
extern "C" void kernel_launch(void* const* d_in, const int* in_sizes, int n_in,
                              void* d_out, int out_size) {
    const float* q0 = (const float*)d_in[0];
    const float* v0 = (const float*)d_in[1];
    const float* q1 = (const float*)d_in[2];
    const float* v1 = (const float*)d_in[3];
    const float* q2 = (const float*)d_in[4];
    const float* v2 = (const float*)d_in[5];
    const float* q3 = (const float*)d_in[6];
    const float* v3 = (const float*)d_in[7];
    const float* vn_g  = (const float*)d_in[8];
    const float* vn_b  = (const float*)d_in[9];
    const float* W_off = (const float*)d_in[10];
    const float* b_off = (const float*)d_in[11];
    const float* W_attn= (const float*)d_in[12];
    const float* b_attn= (const float*)d_in[13];
    const float* W_val = (const float*)d_in[14];
    const float* b_val = (const float*)d_in[15];
    const float* W_out = (const float*)d_in[16];
    const float* b_out = (const float*)d_in[17];
    const float* W_fc1 = (const float*)d_in[18];
    const float* b_fc1 = (const float*)d_in[19];
    const float* W_dw  = (const float*)d_in[20];
    const float* b_dw  = (const float*)d_in[21];
    const float* W_fc2 = (const float*)d_in[22];
    const float* b_fc2 = (const float*)d_in[23];
    float* out = (float*)d_out;

    float *gq, *gv, *gvn, *gval, *goffaw, *gsamp, *gx, *gh1, *gh2;
    float *wtval, *wtoffaw, *boffaw, *wtout, *wtfc1, *wtfc2;
    cudaGetSymbolAddress((void**)&gq,     g_query);
    cudaGetSymbolAddress((void**)&gv,     g_value);
    cudaGetSymbolAddress((void**)&gvn,    g_vn);
    cudaGetSymbolAddress((void**)&gval,   g_val);
    cudaGetSymbolAddress((void**)&goffaw, g_offaw);
    cudaGetSymbolAddress((void**)&gsamp,  g_samp);
    cudaGetSymbolAddress((void**)&gx,     g_x);
    cudaGetSymbolAddress((void**)&gh1,    g_h1);
    cudaGetSymbolAddress((void**)&gh2,    g_h2);
    cudaGetSymbolAddress((void**)&wtval,  g_WT_val);
    cudaGetSymbolAddress((void**)&wtoffaw,g_WT_offaw);
    cudaGetSymbolAddress((void**)&boffaw, g_b_offaw);
    cudaGetSymbolAddress((void**)&wtout,  g_WT_out);
    cudaGetSymbolAddress((void**)&wtfc1,  g_WT_fc1);
    cudaGetSymbolAddress((void**)&wtfc2,  g_WT_fc2);

    cudaFuncSetAttribute(mma_gemm_kernel,
                         cudaFuncAttributeMaxDynamicSharedMemorySize, GEMM_SMEM_BYTES);
    cudaFuncSetAttribute(dwconv_gelu_tiled,
                         cudaFuncAttributeMaxDynamicSharedMemorySize, DW_SMEM_BYTES);

    transpose_all_kernel<<<737, 256>>>(W_val, W_off, W_attn, W_out, W_fc1, W_fc2,
                                       b_off, b_attn,
                                       wtval, wtoffaw, wtout, wtfc1, wtfc2, boffaw);

    flatten_all_kernel<<<2720, 256>>>(q0, v0, q1, v1, q2, v2, q3, v3, gq, gv);

    layernorm_kernel<<<MROWS, 256>>>(gv, vn_g, vn_b, gvn);

    const int MT = MROWS / 128;  // 85
    // val = LN(value) @ W_val + b_val
    mma_gemm_kernel<<<dim3(2, MT), 256, GEMM_SMEM_BYTES>>>(gvn, wtval, b_val, nullptr, gval, DIM, DIM);
    // [off | aw_raw] = query @ [W_off | W_attn] + [b_off | b_attn]
    mma_gemm_kernel<<<dim3(3, MT), 256, GEMM_SMEM_BYTES>>>(gq, wtoffaw, boffaw, nullptr, goffaw, 384, DIM);

    // sampling (softmax fused)
    deform_kernel<<<(MROWS * NH * 32 + 255) / 256, 256>>>(gval, goffaw, gsamp);

    // x = query + samp @ W_out + b_out
    mma_gemm_kernel<<<dim3(2, MT), 256, GEMM_SMEM_BYTES>>>(gsamp, wtout, b_out, gq, gx, DIM, DIM);
    // h1 = x @ W_fc1 + b_fc1
    mma_gemm_kernel<<<dim3(8, MT), 256, GEMM_SMEM_BYTES>>>(gx, wtfc1, b_fc1, nullptr, gh1, HID, DIM);

    // h2 = gelu(dwconv(h1) + b_dw), smem-tiled
    dwconv_gelu_tiled<<<dim3(85, 8, BB), 256, DW_SMEM_BYTES>>>(gh1, W_dw, b_dw, gh2);

    // out = x + h2 @ W_fc2 + b_fc2
    mma_gemm_kernel<<<dim3(2, MT), 256, GEMM_SMEM_BYTES>>>(gh2, wtfc2, b_fc2, gx, out, DIM, HID);
}

// round 11
// speedup vs baseline: 1.2065x; 1.1929x over previous
#include <cuda_runtime.h>
#include <cuda_fp16.h>
#include <math.h>
#include <stdint.h>

// ---------------- problem constants ----------------
#define BB   2
#define DIM  256
#define NH   8
#define HD   32
#define NL   4
#define NP   4
#define HID  1024
#define NQ   5440
#define MROWS (BB*NQ)   // 10880 = 85*128

__device__ __constant__ int LVL_SIZE[4]  = {64, 32, 16, 8};
__device__ __constant__ int LVL_START[4] = {0, 4096, 5120, 5376};

// ---------------- scratch ----------------
__device__ __half g_qh   [(size_t)MROWS * DIM];    // query (half, GEMM A)
__device__ float  g_q32  [(size_t)MROWS * DIM];    // query (fp32, residual)
__device__ float  g_value[(size_t)MROWS * DIM];    // value (fp32, LN input)
__device__ __half g_vnh  [(size_t)MROWS * DIM];    // LN(value) (half, GEMM A)
__device__ float  g_val  [(size_t)MROWS * DIM];    // val (fp32, deform input)
__device__ float  g_offaw[(size_t)MROWS * 384];
__device__ __half g_samph[(size_t)MROWS * DIM];
__device__ float  g_x    [(size_t)MROWS * DIM];    // fp32 residual
__device__ __half g_xh   [(size_t)MROWS * DIM];    // half GEMM A
__device__ float  g_h1   [(size_t)MROWS * HID];
__device__ __half g_h2h  [(size_t)MROWS * HID];
// transposed weights [N, K] in half
__device__ __half g_WT_val  [DIM * DIM];
__device__ __half g_WT_offaw[384 * DIM];
__device__ float  g_b_offaw [384];
__device__ __half g_WT_out  [DIM * DIM];
__device__ __half g_WT_fc1  [HID * DIM];
__device__ __half g_WT_fc2  [DIM * HID];

// ---------------- cp.async helpers ----------------
__device__ __forceinline__ void cp_async16(uint32_t smem, const void* gmem) {
    asm volatile("cp.async.cg.shared.global [%0], [%1], 16;" :: "r"(smem), "l"(gmem));
}
#define CP_COMMIT() asm volatile("cp.async.commit_group;")
#define CP_WAIT0()  asm volatile("cp.async.wait_group 0;")
#define CP_WAIT1()  asm volatile("cp.async.wait_group 1;")

// ---------------- mma.sync m16n8k16 f16 (fp32 accum) ----------------
__device__ __forceinline__ void mma_f16(float* d, const uint32_t* a, const uint32_t* b) {
    asm volatile(
        "mma.sync.aligned.m16n8k16.row.col.f32.f16.f16.f32 "
        "{%0,%1,%2,%3}, {%4,%5,%6,%7}, {%8,%9}, {%0,%1,%2,%3};\n"
        : "+f"(d[0]), "+f"(d[1]), "+f"(d[2]), "+f"(d[3])
        : "r"(a[0]), "r"(a[1]), "r"(a[2]), "r"(a[3]), "r"(b[0]), "r"(b[1]));
}

// ---------------- FP16 tensor-core GEMM, 3-stage cp.async pipeline ----------------
// C[M,N] = A[M,K] @ B[K,N] + bias (+resid fp32); A half [M,K], B half transposed WT[N,K].
// Block tile 128x128, BK=32 (k-halves), 256 threads (8 warps, warp tile 64x32), 3 stages.
// grid = (N/128, M/128). Requires M%128==0, N%128==0, K%32==0, K/32 >= 2.
#define LDH 40                 // halves per smem row (pad 32->40: conflict-free)
#define STG 3
#define STAGE_H (128 * LDH)    // halves per stage per matrix

__global__ void __launch_bounds__(256, 2)
hgemm_kernel(const __half* __restrict__ A, const __half* __restrict__ WT,
             const float* __restrict__ bias, const float* __restrict__ resid,
             float* __restrict__ C, __half* __restrict__ Ch, int N, int K) {
    extern __shared__ __half hsm[];
    __half* Bsmem = hsm + STG * STAGE_H;

    const int t = threadIdx.x;
    const int lane = t & 31;
    const int wid  = t >> 5;
    const int wm = (wid & 1) * 64;
    const int wn = (wid >> 1) * 32;
    const int g   = lane >> 2;
    const int tig = lane & 3;
    const int row0 = blockIdx.y * 128;
    const int col0 = blockIdx.x * 128;

    const uint32_t as_u = (uint32_t)__cvta_generic_to_shared(hsm);
    const uint32_t bs_u = (uint32_t)__cvta_generic_to_shared(Bsmem);

    float acc[4][4][4];
    #pragma unroll
    for (int i = 0; i < 4; i++)
        #pragma unroll
        for (int j = 0; j < 4; j++)
            #pragma unroll
            for (int r = 0; r < 4; r++) acc[i][j][r] = 0.f;

    const int NC = K >> 5;

    // prologue: chunks 0,1 -> stages 0,1
    #pragma unroll
    for (int pc = 0; pc < 2; pc++) {
        const int so = pc * STAGE_H;
        const int k0 = pc << 5;
        #pragma unroll
        for (int j = 0; j < 2; j++) {
            int slot = t + 256 * j;
            int r = slot >> 2, seg = slot & 3;
            cp_async16(as_u + (uint32_t)((so + r * LDH + seg * 8) * 2),
                       A + (size_t)(row0 + r) * K + k0 + seg * 8);
            cp_async16(bs_u + (uint32_t)((so + r * LDH + seg * 8) * 2),
                       WT + (size_t)(col0 + r) * K + k0 + seg * 8);
        }
        CP_COMMIT();
    }

    int stage = 0, pstage = 2;
    for (int c = 0; c < NC; c++) {
        if (c == NC - 1) { CP_WAIT0(); } else { CP_WAIT1(); }
        __syncthreads();
        if (c + 2 < NC) {
            const int so = pstage * STAGE_H;
            const int k0 = (c + 2) << 5;
            #pragma unroll
            for (int j = 0; j < 2; j++) {
                int slot = t + 256 * j;
                int r = slot >> 2, seg = slot & 3;
                cp_async16(as_u + (uint32_t)((so + r * LDH + seg * 8) * 2),
                           A + (size_t)(row0 + r) * K + k0 + seg * 8);
                cp_async16(bs_u + (uint32_t)((so + r * LDH + seg * 8) * 2),
                           WT + (size_t)(col0 + r) * K + k0 + seg * 8);
            }
            CP_COMMIT();
        }
        const __half* Asb = hsm   + stage * STAGE_H;
        const __half* Bsb = Bsmem + stage * STAGE_H;
        #pragma unroll
        for (int ks = 0; ks < 2; ks++) {          // two k16 steps per 32-k chunk
            const int k0h = ks * 16;
            uint32_t bfr[4][2];
            #pragma unroll
            for (int nt = 0; nt < 4; nt++) {
                const __half* p = Bsb + (wn + nt * 8 + g) * LDH + k0h + 2 * tig;
                bfr[nt][0] = *(const uint32_t*)(p);
                bfr[nt][1] = *(const uint32_t*)(p + 8);
            }
            #pragma unroll
            for (int mt = 0; mt < 4; mt++) {
                const __half* p = Asb + (wm + mt * 16 + g) * LDH + k0h + 2 * tig;
                uint32_t afr[4];
                afr[0] = *(const uint32_t*)(p);
                afr[1] = *(const uint32_t*)(p + 8 * LDH);
                afr[2] = *(const uint32_t*)(p + 8);
                afr[3] = *(const uint32_t*)(p + 8 * LDH + 8);
                #pragma unroll
                for (int nt = 0; nt < 4; nt++) mma_f16(acc[mt][nt], afr, bfr[nt]);
            }
        }
        stage = (stage == STG - 1) ? 0 : stage + 1;
        pstage = (pstage == STG - 1) ? 0 : pstage + 1;
    }
    __syncthreads();

    #pragma unroll
    for (int mt = 0; mt < 4; mt++) {
        int r0 = row0 + wm + mt * 16 + g;
        #pragma unroll
        for (int nt = 0; nt < 4; nt++) {
            int cc = col0 + wn + nt * 8 + tig * 2;
            float2 bv = *(const float2*)(bias + cc);
            float2 v0, v1;
            v0.x = acc[mt][nt][0] + bv.x;
            v0.y = acc[mt][nt][1] + bv.y;
            v1.x = acc[mt][nt][2] + bv.x;
            v1.y = acc[mt][nt][3] + bv.y;
            if (resid) {
                float2 ra = *(const float2*)(resid + (size_t)r0 * N + cc);
                float2 rb = *(const float2*)(resid + (size_t)(r0 + 8) * N + cc);
                v0.x += ra.x; v0.y += ra.y;
                v1.x += rb.x; v1.y += rb.y;
            }
            *(float2*)(C + (size_t)r0 * N + cc)       = v0;
            *(float2*)(C + (size_t)(r0 + 8) * N + cc) = v1;
            if (Ch) {
                *(__half2*)(Ch + (size_t)r0 * N + cc)       = __floats2half2_rn(v0.x, v0.y);
                *(__half2*)(Ch + (size_t)(r0 + 8) * N + cc) = __floats2half2_rn(v1.x, v1.y);
            }
        }
    }
}

#define GEMM_SMEM_BYTES (2u * STG * STAGE_H * 2u)   // 61440 B

// ---------------- combined transpose (fp32 -> half [N,K]) + bias concat ----------------
__global__ void __launch_bounds__(256)
transpose_all_kernel(const float* __restrict__ s_val, const float* __restrict__ s_off,
                     const float* __restrict__ s_attn, const float* __restrict__ s_out,
                     const float* __restrict__ s_fc1, const float* __restrict__ s_fc2,
                     const float* __restrict__ b_off, const float* __restrict__ b_attn,
                     __half* __restrict__ d_val, __half* __restrict__ d_offaw,
                     __half* __restrict__ d_out, __half* __restrict__ d_fc1,
                     __half* __restrict__ d_fc2, float* __restrict__ d_b_offaw) {
    int u = blockIdx.x;
    int t = threadIdx.x;
    if (u == 736) {
        if (t < 128) {
            d_b_offaw[t]       = b_off[t];
            d_b_offaw[t + 128] = b_off[t + 128];
        } else {
            int j = t - 128;
            d_b_offaw[256 + j] = b_attn[j];
        }
        return;
    }
    const float* src; __half* dst; int K, N;
    if      (u < 64)  {            src = s_val;  dst = d_val;             K = 256;  N = 256; }
    else if (u < 128) { u -= 64;   src = s_off;  dst = d_offaw;           K = 256;  N = 256; }
    else if (u < 160) { u -= 128;  src = s_attn; dst = d_offaw + 256*256; K = 256;  N = 128; }
    else if (u < 224) { u -= 160;  src = s_out;  dst = d_out;             K = 256;  N = 256; }
    else if (u < 480) { u -= 224;  src = s_fc1;  dst = d_fc1;             K = 256;  N = 1024; }
    else              { u -= 480;  src = s_fc2;  dst = d_fc2;             K = 1024; N = 256; }
    int nt = N >> 5;
    int by = (u / nt) * 32, bx = (u % nt) * 32;
    __shared__ float tile[32][33];
    int tx = t & 31, ty = t >> 5;
    #pragma unroll
    for (int i = 0; i < 32; i += 8)
        tile[ty + i][tx] = src[(size_t)(by + ty + i) * N + bx + tx];
    __syncthreads();
    #pragma unroll
    for (int i = 0; i < 32; i += 8)
        dst[(size_t)(bx + ty + i) * K + by + tx] = __float2half_rn(tile[tx][ty + i]);
}

// ---------------- combined flatten: q -> half + fp32, v -> fp32 ----------------
__global__ void __launch_bounds__(256)
flatten_all_kernel(const float* __restrict__ q0, const float* __restrict__ v0,
                   const float* __restrict__ q1, const float* __restrict__ v1,
                   const float* __restrict__ q2, const float* __restrict__ v2,
                   const float* __restrict__ q3, const float* __restrict__ v3,
                   __half* __restrict__ gqh, float* __restrict__ gq32,
                   float* __restrict__ gv) {
    __shared__ float tq[32][33], tv[32][33];
    int blk = blockIdx.x;
    int b = blk / 1360;
    int u = blk % 1360;
    const float *qs, *vs; int n, start;
    if      (u < 1024) {            qs = q0; vs = v0; n = 4096; start = 0; }
    else if (u < 1280) { u -= 1024; qs = q1; vs = v1; n = 1024; start = 4096; }
    else if (u < 1344) { u -= 1280; qs = q2; vs = v2; n = 256;  start = 5120; }
    else               { u -= 1344; qs = q3; vs = v3; n = 64;   start = 5376; }
    int pt = n >> 5;
    int ct = u / pt;
    int pi = u % pt;
    int t = threadIdx.x;
    int tx = t & 31, ty = t >> 5;
    const float* qb = qs + (size_t)(b * DIM + ct * 32) * n + pi * 32;
    const float* vb = vs + (size_t)(b * DIM + ct * 32) * n + pi * 32;
    #pragma unroll
    for (int i = 0; i < 32; i += 8) {
        tq[ty + i][tx] = qb[(size_t)(ty + i) * n + tx];
        tv[ty + i][tx] = vb[(size_t)(ty + i) * n + tx];
    }
    __syncthreads();
    size_t obase = ((size_t)b * NQ + start + pi * 32) * DIM + ct * 32;
    #pragma unroll
    for (int i = 0; i < 32; i += 8) {
        float qv = tq[tx][ty + i];
        gq32[obase + (size_t)(ty + i) * DIM + tx] = qv;
        gqh [obase + (size_t)(ty + i) * DIM + tx] = __float2half_rn(qv);
        gv  [obase + (size_t)(ty + i) * DIM + tx] = tv[tx][ty + i];
    }
}

// ---------------- layernorm (fp32 in, half out) ----------------
__global__ void layernorm_kernel(const float* __restrict__ x, const float* __restrict__ g,
                                 const float* __restrict__ bia, __half* __restrict__ out) {
    int row = blockIdx.x;
    int t = threadIdx.x;
    float v = x[(size_t)row * DIM + t];
    __shared__ float sm[40];
    float s = v;
    #pragma unroll
    for (int o = 16; o > 0; o >>= 1) s += __shfl_xor_sync(0xffffffffu, s, o);
    if ((t & 31) == 0) sm[t >> 5] = s;
    __syncthreads();
    if (t < 8) {
        float z = sm[t];
        #pragma unroll
        for (int o = 4; o > 0; o >>= 1) z += __shfl_xor_sync(0xffu, z, o);
        if (t == 0) sm[32] = z;
    }
    __syncthreads();
    float mean = sm[32] * (1.0f / DIM);
    float d = v - mean;
    float s2 = d * d;
    #pragma unroll
    for (int o = 16; o > 0; o >>= 1) s2 += __shfl_xor_sync(0xffffffffu, s2, o);
    if ((t & 31) == 0) sm[8 + (t >> 5)] = s2;
    __syncthreads();
    if (t < 8) {
        float z = sm[8 + t];
        #pragma unroll
        for (int o = 4; o > 0; o >>= 1) z += __shfl_xor_sync(0xffu, z, o);
        if (t == 0) sm[33] = z;
    }
    __syncthreads();
    float var = sm[33] * (1.0f / DIM);
    out[(size_t)row * DIM + t] = __float2half_rn(d * rsqrtf(var + 1e-5f) * g[t] + bia[t]);
}

// ---------------- deformable sampling with fused softmax (half out) ----------
__global__ void __launch_bounds__(256)
deform_kernel(const float* __restrict__ val, const float* __restrict__ offaw,
              __half* __restrict__ samp) {
    int gw = (blockIdx.x * blockDim.x + threadIdx.x) >> 5;
    int lane = threadIdx.x & 31;
    if (gw >= MROWS * NH) return;
    int hh = gw % NH;
    int q  = (gw / NH) % NQ;
    int b  = gw / (NH * NQ);

    int lqv, local;
    if (q < 4096)      { lqv = 0; local = q; }
    else if (q < 5120) { lqv = 1; local = q - 4096; }
    else if (q < 5376) { lqv = 2; local = q - 5120; }
    else               { lqv = 3; local = q - 5376; }
    int szq = LVL_SIZE[lqv];
    float refx = ((local % szq) + 0.5f) / szq;
    float refy = ((local / szq) + 0.5f) / szq;

    const float* rowp = offaw + (size_t)(b * NQ + q) * 384;
    const float* offp = rowp + hh * 32;
    const float* awp  = rowp + 256 + hh * 16;

    float awv[16];
    float mx = -1e30f;
    #pragma unroll
    for (int j = 0; j < 16; j++) { awv[j] = awp[j]; mx = fmaxf(mx, awv[j]); }
    float ssum = 0.f;
    #pragma unroll
    for (int j = 0; j < 16; j++) { awv[j] = __expf(awv[j] - mx); ssum += awv[j]; }
    float sinv = 1.0f / ssum;

    float acc = 0.f;
    #pragma unroll
    for (int l = 0; l < NL; l++) {
        int w = LVL_SIZE[l];
        int startl = LVL_START[l];
        const float* vbase = val + ((size_t)b * NQ + startl) * DIM + hh * HD + lane;
        float inv = 1.0f / (float)w;
        #pragma unroll
        for (int p = 0; p < NP; p++) {
            float ox = offp[(l * NP + p) * 2 + 0];
            float oy = offp[(l * NP + p) * 2 + 1];
            float a  = awv[l * NP + p] * sinv;
            float sx = (refx + ox * inv) * w - 0.5f;
            float sy = (refy + oy * inv) * w - 0.5f;
            int x0 = (int)floorf(sx);
            int y0 = (int)floorf(sy);
            float lx = sx - (float)x0;
            float ly = sy - (float)y0;
            float w00 = (1.f - lx) * (1.f - ly);
            float w10 = lx * (1.f - ly);
            float w01 = (1.f - lx) * ly;
            float w11 = lx * ly;
            float g = 0.f;
            if (x0 >= 0 && x0 < w && y0 >= 0 && y0 < w)
                g += w00 * vbase[(size_t)(y0 * w + x0) * DIM];
            if (x0 + 1 >= 0 && x0 + 1 < w && y0 >= 0 && y0 < w)
                g += w10 * vbase[(size_t)(y0 * w + x0 + 1) * DIM];
            if (x0 >= 0 && x0 < w && y0 + 1 >= 0 && y0 + 1 < w)
                g += w01 * vbase[(size_t)((y0 + 1) * w + x0) * DIM];
            if (x0 + 1 >= 0 && x0 + 1 < w && y0 + 1 >= 0 && y0 + 1 < w)
                g += w11 * vbase[(size_t)((y0 + 1) * w + x0 + 1) * DIM];
            acc = fmaf(a, g, acc);
        }
    }
    samp[(size_t)(b * NQ + q) * DIM + hh * HD + lane] = __float2half_rn(acc);
}

// ---------------- depthwise 3x3 + bias + GELU (fp32 in, half out) ----------------
__global__ void __launch_bounds__(256)
dwconv_gelu_tiled(const float* __restrict__ h1, const float* __restrict__ Wdw,
                  const float* __restrict__ bdw, __half* __restrict__ h2) {
    extern __shared__ float ts[];   // [100][128]
    int tile = blockIdx.x;
    int c0 = blockIdx.y * 128;
    int b = blockIdx.z;
    int l, tx, ty;
    if      (tile < 64) { l = 0; ty = tile >> 3; tx = tile & 7; }
    else if (tile < 80) { int u = tile - 64; l = 1; ty = u >> 2; tx = u & 3; }
    else if (tile < 84) { int u = tile - 80; l = 2; ty = u >> 1; tx = u & 1; }
    else                { l = 3; ty = 0; tx = 0; }
    int w = LVL_SIZE[l];
    int start = LVL_START[l];
    int t = threadIdx.x;
    int c = t & 127;
    int half = t >> 7;

    const float* hbase = h1 + ((size_t)b * NQ + start) * HID + c0 + c;
    for (int p = half; p < 100; p += 2) {
        int py = p / 10 - 1 + ty * 8;
        int px = p % 10 - 1 + tx * 8;
        float v = 0.f;
        if (py >= 0 && py < w && px >= 0 && px < w)
            v = hbase[(size_t)(py * w + px) * HID];
        ts[p * 128 + c] = v;
    }
    float w9[9];
    #pragma unroll
    for (int j = 0; j < 9; j++) w9[j] = Wdw[j * HID + c0 + c];
    float bs = bdw[c0 + c];
    __syncthreads();

    __half* obase = h2 + ((size_t)b * NQ + start + (ty * 8) * w + tx * 8) * HID + c0 + c;
    for (int p = half; p < 64; p += 2) {
        int py = p >> 3, px = p & 7;
        float acc = bs;
        #pragma unroll
        for (int ky = 0; ky < 3; ky++)
            #pragma unroll
            for (int kx = 0; kx < 3; kx++)
                acc = fmaf(ts[((py + ky) * 10 + px + kx) * 128 + c], w9[ky * 3 + kx], acc);
        float gelu = acc * 0.5f * (1.0f + erff(acc * 0.70710678118654752440f));
        obase[(size_t)(py * w + px) * HID] = __float2half_rn(gelu);
    }
}
#define DW_SMEM_BYTES (100u * 128u * 4u)   // 51200

// ---------------- launch ----------------
extern "C" void kernel_launch(void* const* d_in, const int* in_sizes, int n_in,
                              void* d_out, int out_size) {
    const float* q0 = (const float*)d_in[0];
    const float* v0 = (const float*)d_in[1];
    const float* q1 = (const float*)d_in[2];
    const float* v1 = (const float*)d_in[3];
    const float* q2 = (const float*)d_in[4];
    const float* v2 = (const float*)d_in[5];
    const float* q3 = (const float*)d_in[6];
    const float* v3 = (const float*)d_in[7];
    const float* vn_g  = (const float*)d_in[8];
    const float* vn_b  = (const float*)d_in[9];
    const float* W_off = (const float*)d_in[10];
    const float* b_off = (const float*)d_in[11];
    const float* W_attn= (const float*)d_in[12];
    const float* b_attn= (const float*)d_in[13];
    const float* W_val = (const float*)d_in[14];
    const float* b_val = (const float*)d_in[15];
    const float* W_out = (const float*)d_in[16];
    const float* b_out = (const float*)d_in[17];
    const float* W_fc1 = (const float*)d_in[18];
    const float* b_fc1 = (const float*)d_in[19];
    const float* W_dw  = (const float*)d_in[20];
    const float* b_dw  = (const float*)d_in[21];
    const float* W_fc2 = (const float*)d_in[22];
    const float* b_fc2 = (const float*)d_in[23];
    float* out = (float*)d_out;

    __half *gqh, *gvnh, *gsamph, *gxh, *gh2h;
    __half *wtval, *wtoffaw, *wtout, *wtfc1, *wtfc2;
    float *gq32, *gv, *gval, *goffaw, *gx, *gh1, *boffaw;
    cudaGetSymbolAddress((void**)&gqh,    g_qh);
    cudaGetSymbolAddress((void**)&gq32,   g_q32);
    cudaGetSymbolAddress((void**)&gv,     g_value);
    cudaGetSymbolAddress((void**)&gvnh,   g_vnh);
    cudaGetSymbolAddress((void**)&gval,   g_val);
    cudaGetSymbolAddress((void**)&goffaw, g_offaw);
    cudaGetSymbolAddress((void**)&gsamph, g_samph);
    cudaGetSymbolAddress((void**)&gx,     g_x);
    cudaGetSymbolAddress((void**)&gxh,    g_xh);
    cudaGetSymbolAddress((void**)&gh1,    g_h1);
    cudaGetSymbolAddress((void**)&gh2h,   g_h2h);
    cudaGetSymbolAddress((void**)&wtval,  g_WT_val);
    cudaGetSymbolAddress((void**)&wtoffaw,g_WT_offaw);
    cudaGetSymbolAddress((void**)&boffaw, g_b_offaw);
    cudaGetSymbolAddress((void**)&wtout,  g_WT_out);
    cudaGetSymbolAddress((void**)&wtfc1,  g_WT_fc1);
    cudaGetSymbolAddress((void**)&wtfc2,  g_WT_fc2);

    cudaFuncSetAttribute(hgemm_kernel,
                         cudaFuncAttributeMaxDynamicSharedMemorySize, GEMM_SMEM_BYTES);
    cudaFuncSetAttribute(dwconv_gelu_tiled,
                         cudaFuncAttributeMaxDynamicSharedMemorySize, DW_SMEM_BYTES);

    transpose_all_kernel<<<737, 256>>>(W_val, W_off, W_attn, W_out, W_fc1, W_fc2,
                                       b_off, b_attn,
                                       wtval, wtoffaw, wtout, wtfc1, wtfc2, boffaw);

    flatten_all_kernel<<<2720, 256>>>(q0, v0, q1, v1, q2, v2, q3, v3, gqh, gq32, gv);

    layernorm_kernel<<<MROWS, 256>>>(gv, vn_g, vn_b, gvnh);

    const int MT = MROWS / 128;  // 85
    // val = LN(value) @ W_val + b_val   (fp32 out for deform)
    hgemm_kernel<<<dim3(2, MT), 256, GEMM_SMEM_BYTES>>>(gvnh, wtval, b_val, nullptr,
                                                        gval, nullptr, DIM, DIM);
    // [off | aw_raw] = query @ [W_off | W_attn] + [b_off | b_attn]
    hgemm_kernel<<<dim3(3, MT), 256, GEMM_SMEM_BYTES>>>(gqh, wtoffaw, boffaw, nullptr,
                                                        goffaw, nullptr, 384, DIM);

    // sampling (softmax fused), half output
    deform_kernel<<<(MROWS * NH * 32 + 255) / 256, 256>>>(gval, goffaw, gsamph);

    // x = query + samp @ W_out + b_out   (fp32 + half outputs)
    hgemm_kernel<<<dim3(2, MT), 256, GEMM_SMEM_BYTES>>>(gsamph, wtout, b_out, gq32,
                                                        gx, gxh, DIM, DIM);
    // h1 = x @ W_fc1 + b_fc1  (fp32 out for dwconv)
    hgemm_kernel<<<dim3(8, MT), 256, GEMM_SMEM_BYTES>>>(gxh, wtfc1, b_fc1, nullptr,
                                                        gh1, nullptr, HID, DIM);

    // h2 = gelu(dwconv(h1) + b_dw), half output
    dwconv_gelu_tiled<<<dim3(85, 8, BB), 256, DW_SMEM_BYTES>>>(gh1, W_dw, b_dw, gh2h);

    // out = x + h2 @ W_fc2 + b_fc2
    hgemm_kernel<<<dim3(2, MT), 256, GEMM_SMEM_BYTES>>>(gh2h, wtfc2, b_fc2, gx,
                                                        out, nullptr, DIM, HID);
}